// round 12
// baseline (speedup 1.0000x reference)
#include <cuda_runtime.h>
#include <cstdint>

// SimplePatchScorer: out[b, j] = dot(W, permuted_patch_row(b, j)) + bias
//   x: (512, 3, 224, 224) fp32, W: (1,768), b: (1,) -> out: (512, 196)
//
// flat[u], u = s*588 + v; s = ph*16+pw; v = c*196 + hn*14 + wn.
// out[b,j] = sum_t W[t]*flat[768j+t] + bias.
// lcm(588,768)=37632 => 4 groups/image: s in [64g,64g+64), j in [49g,49g+49).
//
// v10 = v9 (XOR-swizzled smem, f32x2 phase-2) with:
//  - EIGHTH tiles (8 s' rows = one ph + pw-half; contiguous u' range
//    [4704h, 4704h+4704)), smem 21.9 KB -> 6 CTAs/SM (launch_bounds(256,6)),
//  - 8-way tile-order stagger h0 = ((bid>>2)*5)&7 (walks all 8 phases over
//    +148-spaced co-resident bids) for continuous chip-wide DRAM issue,
//  - tile-invariant precomputed phase-1 offsets (no per-iter carry chain).

#define VPAD    604
#define TILE_U  4704           // 8 * 588
#define THREADS 256

__global__ __launch_bounds__(THREADS, 6)
void patch_scorer_v10(const float* __restrict__ x,
                      const float* __restrict__ W,
                      const float* __restrict__ bias,
                      float* __restrict__ out)
{
    extern __shared__ float smem[];
    float* Y  = smem;               // [8][604], XOR-swizzled granules
    float* Ws = smem + 8 * VPAD;    // [768]

    const int tid  = threadIdx.x;
    const int g    = blockIdx.x & 3;
    const int b    = blockIdx.x >> 2;
    const int lane = tid & 31;
    const int warp = tid >> 5;      // 8 warps

    const float* xb = x + (size_t)b * 150528;
    const uint32_t ybase = (uint32_t)__cvta_generic_to_shared(Y);
    const uint32_t wbase = (uint32_t)__cvta_generic_to_shared(Ws);

    if (tid < 192)                  // 192 float4 = 768 floats
        ((float4*)Ws)[tid] = ((const float4*)W)[tid];
    // visible after the first phase-1 __syncthreads

    // ---- tile-invariant per-thread phase-1 offsets (f = tid + 256k) ----
    // f in [0,1176): q4 = f%28 (wn = q4>>1, kk = q4&1), r = f/28
    //   (hn = r%14, c = r/14); pw-quad = 4*kk (+e), tile row = 4*kk+e.
    // gmem (floats, rel to ph/half base): c*50176 + hn*3584 + wn*16 + 4*kk
    // smem: row = 4kk (+e), col = c*196+hn*14+wn, granule ^= kk (row>>2).
    int goff[5], soff[5];
    #pragma unroll
    for (int k = 0; k < 5; k++) {
        int f  = tid + 256 * k;
        if (f >= 1176) f = 1175;    // masked by pk at use
        int q4 = f % 28;
        int r  = f / 28;
        int wn = q4 >> 1, kk = q4 & 1;
        int hn = r % 14,  c  = r / 14;
        goff[k] = c * 50176 + hn * 3584 + wn * 16 + 4 * kk;
        int col = c * 196 + hn * 14 + wn;
        int xcol = ((((col >> 2) ^ kk) << 2)) | (col & 3);
        soff[k] = (kk << 2) * VPAD + xcol;
    }
    const bool pk4 = (tid < 1176 - 1024);   // slot 4 live for tid < 152

    float acc[7];
    #pragma unroll
    for (int i = 0; i < 7; i++) acc[i] = 0.f;

    const int h0 = ((blockIdx.x >> 2) * 5) & 7;   // 8-way stagger

    for (int hh = 0; hh < 8; hh++) {
        const int h = (h0 + hh) & 7;
        if (hh) __syncthreads();    // previous compute done before overwrite

        // ---- Phase 1: stream tile h -> swizzled smem ----
        {
            const float* bp = xb + (4 * g + (h >> 1)) * 224 + 8 * (h & 1);
            #pragma unroll
            for (int k = 0; k < 5; k++) {
                if (k < 4 || pk4) {
                    float4 val = __ldcs((const float4*)(bp + goff[k]));
                    float* dst = Y + soff[k];
                    dst[0 * VPAD] = val.x;
                    dst[1 * VPAD] = val.y;
                    dst[2 * VPAD] = val.z;
                    dst[3 * VPAD] = val.w;
                }
            }
        }
        __syncthreads();

        // ---- Phase 2: swizzled f32x2 dot over u' in [4704h, 4704h+4704) ----
        const int rlo = TILE_U * h, rhi = rlo + TILE_U;
        #pragma unroll
        for (int i = 0; i < 7; i++) {
            int jl = warp + 8 * i;
            if (jl < 49) {
                int ulo = max(768 * jl, rlo);
                int uhi = min(768 * jl + 768, rhi);
                int u   = ulo + 4 * lane;
                if (u < uhi) {
                    int sp = (unsigned)u / 588u;          // one div per segment
                    int v  = u - sp * 588;
                    int rl = sp - 8 * h;                  // local row 0..7
                    uint32_t ya = ybase + 4u * (rl * VPAD
                                 + ((((v >> 2) ^ (rl >> 2)) << 2) | (v & 3)));
                    uint32_t wa = wbase + 4u * (u - 768 * jl);
                    unsigned long long p01 = 0, p23 = 0;
                    while (u < uhi) {
                        unsigned long long y01, y23, w01, w23;
                        asm volatile("ld.shared.v2.b64 {%0,%1}, [%2];"
                                     : "=l"(y01), "=l"(y23) : "r"(ya));
                        asm volatile("ld.shared.v2.b64 {%0,%1}, [%2];"
                                     : "=l"(w01), "=l"(w23) : "r"(wa));
                        asm volatile("fma.rn.f32x2 %0, %1, %2, %0;"
                                     : "+l"(p01) : "l"(y01), "l"(w01));
                        asm volatile("fma.rn.f32x2 %0, %1, %2, %0;"
                                     : "+l"(p23) : "l"(y23), "l"(w23));
                        u  += 128;            // 32 lanes * 4 floats
                        wa += 512;
                        v  += 128;
                        if (v >= 588) {       // row wrap: re-derive swizzled addr
                            v -= 588; rl++;
                            ya = ybase + 4u * (rl * VPAD
                                 + ((((v >> 2) ^ (rl >> 2)) << 2) | (v & 3)));
                        } else {
                            ya += 512;        // +32 granules; XOR bit0 unaffected
                        }
                    }
                    acc[i] += (__uint_as_float((uint32_t)p01)
                             + __uint_as_float((uint32_t)(p01 >> 32)))
                            + (__uint_as_float((uint32_t)p23)
                             + __uint_as_float((uint32_t)(p23 >> 32)));
                }
            }
        }
    }

    // ---- final warp reductions + store ----
    const float bv = __ldg(bias);
    #pragma unroll
    for (int i = 0; i < 7; i++) {
        int jl = warp + 8 * i;
        if (jl < 49) {
            float a = acc[i];
            #pragma unroll
            for (int off = 16; off; off >>= 1)
                a += __shfl_xor_sync(0xffffffffu, a, off);
            if (lane == 0)
                out[b * 196 + 49 * g + jl] = a + bv;
        }
    }
}

extern "C" void kernel_launch(void* const* d_in, const int* in_sizes, int n_in,
                              void* d_out, int out_size)
{
    const float* x  = (const float*)d_in[0];
    const float* W  = (const float*)d_in[1];
    const float* bb = (const float*)d_in[2];
    float* out = (float*)d_out;

    const int smem_bytes = (8 * VPAD + 768) * sizeof(float);  // ~21.9 KB
    cudaFuncSetAttribute(patch_scorer_v10,
                         cudaFuncAttributeMaxDynamicSharedMemorySize, smem_bytes);

    patch_scorer_v10<<<512 * 4, THREADS, smem_bytes>>>(x, W, bb, out);
}